// round 1
// baseline (speedup 1.0000x reference)
#include <cuda_runtime.h>

// URPE: out[b,h,i,j] = probs[b,h,i,j] * toe[h,i,j]
// toe[h,i,j] = (j>=i) ? w[h, 2048 + (j-i)] : w[h, i-j]
// B=2, H=16, L=2048, weights are (16, 4096) f32.
//
// Pure HBM-streaming kernel: 536.9 MB read + 536.9 MB write. Weight table
// (256 KB total, 16 KB/head) lives in L1/L2; gathered scalar per element.

#define L_DIM 2048
#define H_DIM 16

__global__ __launch_bounds__(512, 4)
void urpe_kernel(const float4* __restrict__ probs,
                 const float* __restrict__ w,
                 float4* __restrict__ out)
{
    // One float4 per thread. Total float4s = 2*16*2048*2048/4 = 33,554,432.
    unsigned int idx = blockIdx.x * 512u + threadIdx.x;

    // Decompose: row-major (b,h,i,j4) with j4 in [0,512)
    int j = (int)((idx & 511u) << 2);        // starting column of this float4
    unsigned int row = idx >> 9;             // (b*16 + h)*2048 + i
    int i = (int)(row & 2047u);
    int h = (int)((row >> 11) & 15u);

    const float* wh = w + h * (2 * L_DIM);

    float4 v = probs[idx];

    int d = j - i;
    float t0 = wh[d >= 0 ? 2048 + d : -d]; d++;
    float t1 = wh[d >= 0 ? 2048 + d : -d]; d++;
    float t2 = wh[d >= 0 ? 2048 + d : -d]; d++;
    float t3 = wh[d >= 0 ? 2048 + d : -d];

    float4 r;
    r.x = v.x * t0;
    r.y = v.y * t1;
    r.z = v.z * t2;
    r.w = v.w * t3;
    out[idx] = r;
}

extern "C" void kernel_launch(void* const* d_in, const int* in_sizes, int n_in,
                              void* d_out, int out_size)
{
    const float4* probs = (const float4*)d_in[0];   // (2,16,2048,2048) f32
    const float*  w     = (const float*)d_in[1];    // (16, 4096) f32
    float4* out = (float4*)d_out;

    // total float4 elements = 33,554,432 -> 65536 blocks of 512 threads
    urpe_kernel<<<65536, 512>>>(probs, w, out);
}

// round 2
// speedup vs baseline: 1.1002x; 1.1002x over previous
#include <cuda_runtime.h>

// URPE: out[b,h,i,j] = probs[b,h,i,j] * toe[h,i,j]
// toe[h,i,j] = (j>=i) ? w[h, 2048 + (j-i)] : w[h, i-j]
// B=2, H=16, L=2048, weights (16, 4096) f32.
//
// One block per row (b,h,i). Stage the 2048-float Toeplitz row in smem with a
// coalesced cooperative gather (64 L1 wavefronts/row instead of 256 for the
// naive per-thread scalar gathers), then stream probs*toe with float4s.

#define L_DIM 2048

__global__ __launch_bounds__(256, 8)
void urpe_kernel(const float4* __restrict__ probs,
                 const float* __restrict__ w,
                 float4* __restrict__ out)
{
    __shared__ float toe_row[L_DIM];

    const unsigned int row = blockIdx.x;          // ((b*16+h)*2048 + i)
    const int i = (int)(row & 2047u);
    const int h = (int)((row >> 11) & 15u);
    const float* __restrict__ wh = w + h * (2 * L_DIM);

    const int tid = threadIdx.x;

    // Cooperative fill: consecutive tid -> consecutive j -> contiguous weight
    // addresses (ascending for j>=i, descending-contiguous for j<i).
    #pragma unroll
    for (int j = tid; j < L_DIM; j += 256) {
        int d = j - i;
        toe_row[j] = __ldg(&wh[d >= 0 ? 2048 + d : -d]);
    }
    __syncthreads();

    const float4* __restrict__ toe4 = (const float4*)toe_row;
    const unsigned long long base = (unsigned long long)row * 512ull;

    // Each thread: 2 float4s (columns 4*tid.. and 4*(tid+256)..)
    #pragma unroll
    for (int k = 0; k < 2; ++k) {
        unsigned int c = tid + k * 256;           // float4 column index [0,512)
        float4 v = probs[base + c];
        float4 t = toe4[c];
        float4 r;
        r.x = v.x * t.x;
        r.y = v.y * t.y;
        r.z = v.z * t.z;
        r.w = v.w * t.w;
        out[base + c] = r;
    }
}

extern "C" void kernel_launch(void* const* d_in, const int* in_sizes, int n_in,
                              void* d_out, int out_size)
{
    const float4* probs = (const float4*)d_in[0];   // (2,16,2048,2048) f32
    const float*  w     = (const float*)d_in[1];    // (16, 4096) f32
    float4* out = (float4*)d_out;

    // 2*16*2048 = 65536 rows, one block each
    urpe_kernel<<<65536, 256>>>(probs, w, out);
}